// round 12
// baseline (speedup 1.0000x reference)
#include <cuda_runtime.h>

// MaxOccurrencePool: sliding-window (K=9, span [l-3,l+5]) mode-with-tie-average +
// max-count over integer values 0..4 (1..4 counted; bin0 only when window empty).
// x: [B=8, L=131072, C=16] f32. Outputs: out [B,L-1,C] f32 then density [B,L-1,C] f32.
//
// R9: no register ring — evicted value re-read from staged smem (1 LDS.128),
//     one-hot built directly from float (FADD magic + LOP + funnelshift, no fint).
//     Frees ~10 regs and the mod-9 constraint: U=7, TILE=56, smem 34.8KB ->
//     6 CTAs/SM (75% occ theoretical). Consume = R8 shifted-max + 160-float2 LUT.

#define BB    8
#define LL    131072
#define LOUT  131071               // L - 1 output positions
#define U     7                    // outputs per warp
#define WPB   8                    // warps per CTA
#define TILE  (U * WPB)            // 56 outputs per CTA
#define NBLK  ((LOUT + TILE - 1) / TILE)   // 2341
#define S     (TILE + 10)          // staged positions per batch: [l0-4, l0+TILE+5]
#define BSTR  ((S + 1) * 64)       // per-batch smem stride (pad 64B)
#define MAGIC 8388608.0f           // 2^23

// one-hot byte straight from float value 0..4: byte (iv-1)=1, or 0 for iv==0
__device__ __forceinline__ unsigned ohf(float f) {
    unsigned bits = __float_as_uint(f + MAGIC);
    unsigned amt  = (bits << 3) & 0x38u;            // (iv&7)*8
    return __funnelshift_lc(0x01000000u, 0u, amt);  // clamped shift
}

// h = packed byte counts -> (out, den) via smem LUT. Counts <= 9 (high nibbles 0).
__device__ __forceinline__ float2 consume(unsigned h, const float2 *__restrict__ lut) {
    unsigned z = max(h, h << 8);
    z = max(z, h << 16);
    z = max(z, h << 24);                    // top byte of z = m
    unsigned t = (h + 0x10101010u) - (z >> 24) * 0x01010101u;
    unsigned mskb = (t >> 4) & 0x01010101u; // 1 per tied byte
    unsigned idx  = __dp4a(mskb, 0x08040201u, z >> 20);  // m*16 + pattern
    return lut[idx];
}

__global__ void __launch_bounds__(256, 6)
MaxOccurrencePool_kernel(const float *__restrict__ x, float *__restrict__ out) {
    __shared__ __align__(16) char sm[BB * BSTR];
    __shared__ __align__(8) float2 lut[160];

    const int tid = threadIdx.x;
    const int l0cta = blockIdx.x * TILE;

    // ---- stage tile: x[b][l0cta-4 .. l0cta+TILE+5][16ch] via cp.async (zfill OOB)
    {
        const int total = BB * S * 4;              // 16B chunks
        #pragma unroll
        for (int t = tid; t < total; t += 256) {
            int b  = t / (S * 4);
            int r  = t - b * (S * 4);
            int li = r >> 2;
            int cg = r & 3;
            int p  = l0cta - 4 + li;
            unsigned ok = ((unsigned)p < (unsigned)LL);
            unsigned sz = ok ? 16u : 0u;
            int pc = ok ? p : 0;
            const float *g = x + ((size_t)b * LL + pc) * 16 + cg * 4;
            unsigned sa = (unsigned)__cvta_generic_to_shared(sm + b * BSTR + li * 64 + cg * 16);
            asm volatile("cp.async.cg.shared.global [%0], [%1], 16, %2;"
                         :: "r"(sa), "l"(g), "r"(sz));
        }
        asm volatile("cp.async.commit_group;");
    }

    // ---- build consume LUT while cp.async is in flight ----
    if (tid < 160) {
        unsigned m = tid >> 4, pat = tid & 15u;
        unsigned n = __popc(pat);
        unsigned s = (pat & 1u) + 2u * ((pat >> 1) & 1u)
                   + 3u * ((pat >> 2) & 1u) + 4u * ((pat >> 3) & 1u);
        float o = (m && n) ? __fdividef((float)s, (float)n) : 0.0f;
        lut[tid] = make_float2(o, (float)max(m, 1u));
    }

    asm volatile("cp.async.wait_group 0;");
    __syncthreads();

    const int w    = tid >> 5;
    const int lane = tid & 31;
    const int cg   = lane & 3;        // channel group (4 floats)
    const int b    = lane >> 2;       // batch
    const int l0   = l0cta + w * U;   // this warp's first output

    // smem element idx i (position p = l0cta-4+i) lives at sp[i*4] (float4)
    const float4 *sp = reinterpret_cast<const float4 *>(sm + b * BSTR + cg * 16);
    const int base = w * U;           // idx of position l0-4

    unsigned h0 = 0, h1 = 0, h2 = 0, h3 = 0;

    // Prefill window: positions l0-4 .. l0+4 (idx base..base+8)
    #pragma unroll
    for (int k = 0; k < 9; k++) {
        float4 v = sp[(base + k) * 4];
        h0 += ohf(v.x); h1 += ohf(v.y); h2 += ohf(v.z); h3 += ohf(v.w);
    }

    float4 *outp = reinterpret_cast<float4 *>(out) + (size_t)b * LOUT * 4 + cg;
    float4 *denp = outp + (size_t)BB * LOUT * 4;   // density tensor follows out

    // U steps; step j: incoming idx base+9+j, evicted idx base+j (from smem)
    #pragma unroll
    for (int j = 0; j < U; j++) {
        int l = l0 + j;
        float4 vi = sp[(base + 9 + j) * 4];
        float4 ve = sp[(base + j) * 4];

        h0 += ohf(vi.x) - ohf(ve.x);
        h1 += ohf(vi.y) - ohf(ve.y);
        h2 += ohf(vi.z) - ohf(ve.z);
        h3 += ohf(vi.w) - ohf(ve.w);

        float2 r0 = consume(h0, lut);
        float2 r1 = consume(h1, lut);
        float2 r2 = consume(h2, lut);
        float2 r3 = consume(h3, lut);

        if (l < LOUT) {
            __stcs(&outp[l * 4], make_float4(r0.x, r1.x, r2.x, r3.x));
            __stcs(&denp[l * 4], make_float4(r0.y, r1.y, r2.y, r3.y));
        }
    }
}

extern "C" void kernel_launch(void* const* d_in, const int* in_sizes, int n_in,
                              void* d_out, int out_size) {
    const float *x = (const float *)d_in[0];
    float *out = (float *)d_out;
    MaxOccurrencePool_kernel<<<NBLK, 256>>>(x, out);
}

// round 13
// speedup vs baseline: 1.0515x; 1.0515x over previous
#include <cuda_runtime.h>

// MaxOccurrencePool: sliding-window (K=9, span [l-3,l+5]) mode-with-tie-average +
// max-count over integer values 0..4 (1..4 counted; bin0 only when window empty).
// x: [B=8, L=131072, C=16] f32. Outputs: out [B,L-1,C] f32 then density [B,L-1,C] f32.
//
// R10: R8 structure (register nibble ring, U=9, shifted-max + 160-float2 LUT
//      consume) with input staging moved to TMA: interior CTAs load their tile
//      as 8x cp.async.bulk (1D, 5248B per batch) completed on an mbarrier,
//      replacing ~2624 LDGSTS (rt=8) + div/mod addressing (~14% of warp issue).
//      Boundary CTAs (need zfill) keep the per-chunk cp.async path.

#define BB    8
#define LL    131072
#define LOUT  131071               // L - 1 output positions
#define U     9                    // outputs per warp (= ring period)
#define WPB   8                    // warps per CTA
#define TILE  (U * WPB)            // 72 outputs per CTA
#define NBLK  ((LOUT + TILE - 1) / TILE)   // 1821
#define S     (TILE + 10)          // staged positions per batch: [l0-4, l0+TILE+5]
#define BSTR  ((S + 1) * 64)       // per-batch smem stride (pad 64B), mult of 16
#define MAGIC 8388608.0f           // 2^23

// one-hot byte for value iv in 0..4: byte (iv-1) = 1, or 0 for iv==0
__device__ __forceinline__ unsigned oh(unsigned iv) {
    return __funnelshift_lc(0x01000000u, 0u, iv << 3);
}
__device__ __forceinline__ unsigned fint(float f) {
    return __float_as_uint(f + MAGIC) & 7u;   // exact for integer-valued 0..4
}

// h = packed byte counts -> (out, den) via smem LUT. Counts <= 9 (high nibbles 0).
__device__ __forceinline__ float2 consume(unsigned h, const float2 *__restrict__ lut) {
    unsigned z = max(h, h << 8);
    z = max(z, h << 16);
    z = max(z, h << 24);                    // top byte of z = m
    unsigned t = (h + 0x10101010u) - (z >> 24) * 0x01010101u;
    unsigned mskb = (t >> 4) & 0x01010101u; // 1 per tied byte
    unsigned idx  = __dp4a(mskb, 0x08040201u, z >> 20);  // m*16 + pattern
    return lut[idx];
}

__global__ void __launch_bounds__(256, 5)
MaxOccurrencePool_kernel(const float *__restrict__ x, float *__restrict__ out) {
    __shared__ __align__(16) char sm[BB * BSTR];
    __shared__ __align__(8) float2 lut[160];
    __shared__ __align__(8) unsigned long long mbar;

    const int tid = threadIdx.x;
    const int l0cta = blockIdx.x * TILE;
    // interior iff staged range [l0cta-4, l0cta-4+S) fully inside [0, LL)
    const bool interior = (l0cta >= 4) && (l0cta - 4 + S <= LL);

    if (interior) {
        if (tid == 0) {
            unsigned ma = (unsigned)__cvta_generic_to_shared(&mbar);
            asm volatile("mbarrier.init.shared.b64 [%0], 1;" :: "r"(ma) : "memory");
        }
        __syncthreads();
        if (tid == 0) {
            unsigned ma = (unsigned)__cvta_generic_to_shared(&mbar);
            asm volatile("mbarrier.arrive.expect_tx.shared.b64 _, [%0], %1;"
                         :: "r"(ma), "r"(BB * S * 64) : "memory");
            #pragma unroll
            for (int b = 0; b < BB; b++) {
                const float *g = x + ((size_t)b * LL + (l0cta - 4)) * 16;
                unsigned sa = (unsigned)__cvta_generic_to_shared(sm + b * BSTR);
                asm volatile(
                    "cp.async.bulk.shared::cta.global.mbarrier::complete_tx::bytes "
                    "[%0], [%1], %2, [%3];"
                    :: "r"(sa), "l"(g), "r"(S * 64), "r"(ma) : "memory");
            }
        }
    } else {
        // boundary: per-chunk cp.async with zfill for OOB positions
        const int total = BB * S * 4;              // 16B chunks
        #pragma unroll 1
        for (int t = tid; t < total; t += 256) {
            int b  = t / (S * 4);
            int r  = t - b * (S * 4);
            int li = r >> 2;
            int cg = r & 3;
            int p  = l0cta - 4 + li;
            unsigned ok = ((unsigned)p < (unsigned)LL);
            unsigned sz = ok ? 16u : 0u;
            int pc = ok ? p : 0;
            const float *g = x + ((size_t)b * LL + pc) * 16 + cg * 4;
            unsigned sa = (unsigned)__cvta_generic_to_shared(sm + b * BSTR + li * 64 + cg * 16);
            asm volatile("cp.async.cg.shared.global [%0], [%1], 16, %2;"
                         :: "r"(sa), "l"(g), "r"(sz));
        }
        asm volatile("cp.async.commit_group;");
    }

    // ---- build consume LUT while loads are in flight ----
    if (tid < 160) {
        unsigned m = tid >> 4, pat = tid & 15u;
        unsigned n = __popc(pat);
        unsigned s = (pat & 1u) + 2u * ((pat >> 1) & 1u)
                   + 3u * ((pat >> 2) & 1u) + 4u * ((pat >> 3) & 1u);
        float o = (m && n) ? __fdividef((float)s, (float)n) : 0.0f;
        lut[tid] = make_float2(o, (float)max(m, 1u));
    }

    if (interior) {
        unsigned ma = (unsigned)__cvta_generic_to_shared(&mbar);
        unsigned done;
        asm volatile(
            "{\n\t.reg .pred p;\n\t"
            "mbarrier.try_wait.parity.acquire.cta.shared::cta.b64 p, [%1], 0;\n\t"
            "selp.b32 %0, 1, 0, p;\n\t}"
            : "=r"(done) : "r"(ma) : "memory");
        while (!done) {
            asm volatile(
                "{\n\t.reg .pred p;\n\t"
                "mbarrier.try_wait.parity.acquire.cta.shared::cta.b64 p, [%1], 0, 0x989680;\n\t"
                "selp.b32 %0, 1, 0, p;\n\t}"
                : "=r"(done) : "r"(ma) : "memory");
        }
    } else {
        asm volatile("cp.async.wait_group 0;");
    }
    __syncthreads();   // LUT visibility + all threads past load wait

    const int w    = tid >> 5;
    const int lane = tid & 31;
    const int cg   = lane & 3;        // channel group (4 floats)
    const int b    = lane >> 2;       // batch
    const int l0   = l0cta + w * U;   // this warp's first output

    // smem element idx i (position p = l0cta-4+i) lives at sp[i*4] (float4)
    const float4 *sp = reinterpret_cast<const float4 *>(sm + b * BSTR + cg * 16);
    const int base = w * U;           // idx of position l0-4

    unsigned h0 = 0, h1 = 0, h2 = 0, h3 = 0;
    unsigned ring[9];                 // nibble-packed raw values of 4 channels

    // Prefill slots k=0..8 with positions l0-4..l0+4 (idx base+k)
    #pragma unroll
    for (int k = 0; k < 9; k++) {
        float4 v = sp[(base + k) * 4];
        unsigned i0 = fint(v.x), i1 = fint(v.y), i2 = fint(v.z), i3 = fint(v.w);
        ring[k] = i0 | (i1 << 4) | (i2 << 8) | (i3 << 12);
        h0 += oh(i0); h1 += oh(i1); h2 += oh(i2); h3 += oh(i3);
    }

    float4 *outp = reinterpret_cast<float4 *>(out) + (size_t)b * LOUT * 4 + cg;
    float4 *denp = outp + (size_t)BB * LOUT * 4;   // density tensor follows out

    // 9 steps; step j: incoming position l0+5+j (idx base+9+j), evict slot j
    #pragma unroll
    for (int j = 0; j < U; j++) {
        int l = l0 + j;
        float4 v = sp[(base + 9 + j) * 4];
        unsigned i0 = fint(v.x), i1 = fint(v.y), i2 = fint(v.z), i3 = fint(v.w);

        unsigned old = ring[j];
        ring[j] = i0 | (i1 << 4) | (i2 << 8) | (i3 << 12);

        unsigned od0 = __funnelshift_lc(0x01000000u, 0u, (old << 3) & 0x78u);
        unsigned od1 = __funnelshift_lc(0x01000000u, 0u, (old >> 1) & 0x78u);
        unsigned od2 = __funnelshift_lc(0x01000000u, 0u, (old >> 5) & 0x78u);
        unsigned od3 = __funnelshift_lc(0x01000000u, 0u, (old >> 9) & 0x78u);

        h0 += oh(i0) - od0;
        h1 += oh(i1) - od1;
        h2 += oh(i2) - od2;
        h3 += oh(i3) - od3;

        float2 r0 = consume(h0, lut);
        float2 r1 = consume(h1, lut);
        float2 r2 = consume(h2, lut);
        float2 r3 = consume(h3, lut);

        if (l < LOUT) {
            __stcs(&outp[l * 4], make_float4(r0.x, r1.x, r2.x, r3.x));
            __stcs(&denp[l * 4], make_float4(r0.y, r1.y, r2.y, r3.y));
        }
    }
}

extern "C" void kernel_launch(void* const* d_in, const int* in_sizes, int n_in,
                              void* d_out, int out_size) {
    const float *x = (const float *)d_in[0];
    float *out = (float *)d_out;
    MaxOccurrencePool_kernel<<<NBLK, 256>>>(x, out);
}